// round 2
// baseline (speedup 1.0000x reference)
#include <cuda_runtime.h>

#define NN 1024
#define BB 4
#define HH 32

// 4 MB scratch for the normalized, diagonal-masked softmax adjacency.
__device__ float g_A[NN * NN];

// ---------------- packed f32x2 helpers (sm_100+) ----------------
static __device__ __forceinline__ unsigned long long pack2(float lo, float hi) {
    unsigned long long r;
    asm("mov.b64 %0, {%1, %2};" : "=l"(r) : "f"(lo), "f"(hi));
    return r;
}
static __device__ __forceinline__ void unpack2(unsigned long long v, float& lo, float& hi) {
    asm("mov.b64 {%0, %1}, %2;" : "=f"(lo), "=f"(hi) : "l"(v));
}
static __device__ __forceinline__ unsigned long long fma2(unsigned long long a,
                                                          unsigned long long b,
                                                          unsigned long long c) {
    unsigned long long d;
    asm("fma.rn.f32x2 %0, %1, %2, %3;" : "=l"(d) : "l"(a), "l"(b), "l"(c));
    return d;
}
static __device__ __forceinline__ unsigned long long add2(unsigned long long a,
                                                          unsigned long long b) {
    unsigned long long d;
    asm("add.rn.f32x2 %0, %1, %2;" : "=l"(d) : "l"(a), "l"(b));
    return d;
}
static __device__ __forceinline__ float tanhx(float x) {
    float y;
    asm("tanh.approx.f32 %0, %1;" : "=f"(y) : "f"(x));
    return y;
}
static __device__ __forceinline__ unsigned long long tanh2(unsigned long long v) {
    float lo, hi;
    unpack2(v, lo, hi);
    return pack2(tanhx(lo), tanhx(hi));
}

// ---------------- Kernel 1: masked row softmax of Theta -> g_A ----------------
__global__ __launch_bounds__(256) void softmax_kernel(const float* __restrict__ Theta) {
    int i = blockIdx.x;
    int t = threadIdx.x;
    const float* row = Theta + (size_t)i * NN;

    float vals[4];
    float m = -3.4e38f;
#pragma unroll
    for (int u = 0; u < 4; u++) {
        vals[u] = row[t + 256 * u];
        m = fmaxf(m, vals[u]);
    }
#pragma unroll
    for (int o = 16; o; o >>= 1) m = fmaxf(m, __shfl_xor_sync(0xffffffffu, m, o));

    __shared__ float redmax[8], redsum[8];
    if ((t & 31) == 0) redmax[t >> 5] = m;
    __syncthreads();
    float m0 = redmax[0];
#pragma unroll
    for (int w = 1; w < 8; w++) m0 = fmaxf(m0, redmax[w]);

    float s = 0.f;
#pragma unroll
    for (int u = 0; u < 4; u++) {
        int j = t + 256 * u;
        float e = __expf(vals[u] - m0);
        if (j == i) e = 0.f;
        vals[u] = e;
        s += e;
    }
#pragma unroll
    for (int o = 16; o; o >>= 1) s += __shfl_xor_sync(0xffffffffu, s, o);
    if ((t & 31) == 0) redsum[t >> 5] = s;
    __syncthreads();
    float tot = 0.f;
#pragma unroll
    for (int w = 0; w < 8; w++) tot += redsum[w];
    float inv = 1.0f / tot;
#pragma unroll
    for (int u = 0; u < 4; u++) g_A[(size_t)i * NN + t + 256 * u] = vals[u] * inv;
}

// ---------------- Kernel 2: pairwise MLP gate + aggregation ----------------
// One block per (b, i). 512 threads, 2 j's per thread as ONE packed f32x2 unit.
// Register budget ~100 -> 16 warps/SM (4 per SMSP) for latency hiding.
__global__ __launch_bounds__(512, 1) void agg_kernel(
    const float* __restrict__ x,
    const float* __restrict__ W1, const float* __restrict__ b1,
    const float* __restrict__ W2, const float* __restrict__ b2,
    const float* __restrict__ W3, const float* __restrict__ b3,
    float* __restrict__ out) {
    // W2 duplicated into both f32x2 lanes; rows 256B -> every row 16B aligned.
    __shared__ __align__(16) unsigned long long sW2[HH][HH];
    __shared__ unsigned long long sC0[HH];   // (W1[m][0]-W1[m][2])*xi + b1[m]   (dup)
    __shared__ unsigned long long sW12[HH];  // W1[m][1]+W1[m][2]                (dup)
    __shared__ unsigned long long sB2[HH];   // b2[m]                            (dup)
    __shared__ unsigned long long sW3[HH];   // W3[0][m]                         (dup)
    __shared__ float warpsum[16];

    int t = threadIdx.x;
    int bi = blockIdx.x;
    int b = bi >> 10;
    int i = bi & (NN - 1);
    const float* xb = x + b * NN;
    float xi = xb[i];

    for (int idx = t; idx < HH * HH; idx += 512) {
        float w = W2[idx];
        sW2[idx >> 5][idx & 31] = pack2(w, w);
    }
    if (t < HH) {
        int m = t;
        float w0 = W1[3 * m + 0];
        float w1v = W1[3 * m + 1];
        float w2v = W1[3 * m + 2];
        float c0 = fmaf(w0 - w2v, xi, b1[m]);
        sC0[m] = pack2(c0, c0);
        float w12 = w1v + w2v;
        sW12[m] = pack2(w12, w12);
        float bb = b2[m];
        sB2[m] = pack2(bb, bb);
        float w3 = W3[m];
        sW3[m] = pack2(w3, w3);
    }
    __syncthreads();

    int j0 = t, j1 = t + 512;
    float xj0 = xb[j0], xj1 = xb[j1];
    unsigned long long xjA = pack2(xj0, xj1);

    // Layer 1: h1[m] = tanh( c0[m] + (w1+w2)[m] * xj )   [feats folded]
    unsigned long long h1[HH];
#pragma unroll
    for (int m = 0; m < HH; m++) {
        h1[m] = tanh2(fma2(xjA, sW12[m], sC0[m]));
    }

    // Layers 2+3 fused: raw += W3[m] * tanh(b2[m] + sum_k h1[k]*W2[m][k])
    // 4 accumulator chains -> fma reuse distance 4 instrs >= fma latency.
    float b3v = b3[0];
    unsigned long long raw = pack2(b3v, b3v);
    const unsigned long long zero2 = pack2(0.f, 0.f);

#pragma unroll 4
    for (int m = 0; m < HH; m++) {
        const ulonglong2* wr = reinterpret_cast<const ulonglong2*>(&sW2[m][0]);
        unsigned long long a0 = sB2[m];
        unsigned long long a1 = zero2;
        unsigned long long a2 = zero2;
        unsigned long long a3 = zero2;
#pragma unroll
        for (int k4 = 0; k4 < HH / 4; k4++) {
            ulonglong2 w01 = wr[2 * k4];      // LDS.128 broadcast (dup-packed pair)
            ulonglong2 w23 = wr[2 * k4 + 1];
            a0 = fma2(h1[4 * k4 + 0], w01.x, a0);
            a1 = fma2(h1[4 * k4 + 1], w01.y, a1);
            a2 = fma2(h1[4 * k4 + 2], w23.x, a2);
            a3 = fma2(h1[4 * k4 + 3], w23.y, a3);
        }
        unsigned long long h = tanh2(add2(add2(a0, a1), add2(a2, a3)));
        raw = fma2(h, sW3[m], raw);
    }

    // alpha = 2*sigmoid(raw) = 1 + tanh(raw/2)    (ALPHA_MIN=0, ALPHA_MAX=2)
    float r0, r1;
    unpack2(raw, r0, r1);
    float al0 = 1.f + tanhx(0.5f * r0);
    float al1 = 1.f + tanhx(0.5f * r1);

    // A[i,i] = 0 and diff(i,i) = 0, so no diagonal special-casing needed.
    const float* Ar = g_A + (size_t)i * NN;
    float acc = Ar[j0] * al0 * (xj0 - xi)
              + Ar[j1] * al1 * (xj1 - xi);

    // block reduction over 512 threads
#pragma unroll
    for (int o = 16; o; o >>= 1) acc += __shfl_xor_sync(0xffffffffu, acc, o);
    if ((t & 31) == 0) warpsum[t >> 5] = acc;
    __syncthreads();
    if (t == 0) {
        float s = 0.f;
#pragma unroll
        for (int w = 0; w < 16; w++) s += warpsum[w];
        out[b * NN + i] = fmaf(0.1f, s, xi);
    }
}

extern "C" void kernel_launch(void* const* d_in, const int* in_sizes, int n_in,
                              void* d_out, int out_size) {
    (void)in_sizes; (void)n_in; (void)out_size;
    const float* x  = (const float*)d_in[0];
    const float* Th = (const float*)d_in[1];
    const float* W1 = (const float*)d_in[2];
    const float* b1 = (const float*)d_in[3];
    const float* W2 = (const float*)d_in[4];
    const float* b2 = (const float*)d_in[5];
    const float* W3 = (const float*)d_in[6];
    const float* b3 = (const float*)d_in[7];
    float* out = (float*)d_out;

    softmax_kernel<<<NN, 256>>>(Th);
    agg_kernel<<<BB * NN, 512>>>(x, W1, b1, W2, b2, W3, b3, out);
}

// round 3
// speedup vs baseline: 2.9425x; 2.9425x over previous
#include <cuda_runtime.h>

#define NN 1024
#define BB 4
#define HH 32

// 4 MB scratch for the normalized, diagonal-masked softmax adjacency.
__device__ float g_A[NN * NN];

static __device__ __forceinline__ float tanhx(float x) {
    float y;
    asm("tanh.approx.f32 %0, %1;" : "=f"(y) : "f"(x));
    return y;
}
static __device__ __forceinline__ unsigned tf32(float f) {
    unsigned r;
    asm("cvt.rna.tf32.f32 %0, %1;" : "=r"(r) : "f"(f));
    return r;
}
// D += A(m16k8, tf32) * B(k8n8, tf32), fp32 accumulate.
static __device__ __forceinline__ void mma_tf32(
    float& d0, float& d1, float& d2, float& d3,
    unsigned a0, unsigned a1, unsigned a2, unsigned a3,
    unsigned b0, unsigned b1) {
    asm("mma.sync.aligned.m16n8k8.row.col.f32.tf32.tf32.f32 "
        "{%0,%1,%2,%3},{%4,%5,%6,%7},{%8,%9},{%0,%1,%2,%3};"
        : "+f"(d0), "+f"(d1), "+f"(d2), "+f"(d3)
        : "r"(a0), "r"(a1), "r"(a2), "r"(a3), "r"(b0), "r"(b1));
}

// ---------------- Kernel 1: masked row softmax of Theta -> g_A ----------------
__global__ __launch_bounds__(256) void softmax_kernel(const float* __restrict__ Theta) {
    int i = blockIdx.x;
    int t = threadIdx.x;
    const float* row = Theta + (size_t)i * NN;

    float vals[4];
    float m = -3.4e38f;
#pragma unroll
    for (int u = 0; u < 4; u++) {
        vals[u] = row[t + 256 * u];
        m = fmaxf(m, vals[u]);
    }
#pragma unroll
    for (int o = 16; o; o >>= 1) m = fmaxf(m, __shfl_xor_sync(0xffffffffu, m, o));

    __shared__ float redmax[8], redsum[8];
    if ((t & 31) == 0) redmax[t >> 5] = m;
    __syncthreads();
    float m0 = redmax[0];
#pragma unroll
    for (int w = 1; w < 8; w++) m0 = fmaxf(m0, redmax[w]);

    float s = 0.f;
#pragma unroll
    for (int u = 0; u < 4; u++) {
        int j = t + 256 * u;
        float e = __expf(vals[u] - m0);
        if (j == i) e = 0.f;
        vals[u] = e;
        s += e;
    }
#pragma unroll
    for (int o = 16; o; o >>= 1) s += __shfl_xor_sync(0xffffffffu, s, o);
    if ((t & 31) == 0) redsum[t >> 5] = s;
    __syncthreads();
    float tot = 0.f;
#pragma unroll
    for (int w = 0; w < 8; w++) tot += redsum[w];
    float inv = 1.0f / tot;
#pragma unroll
    for (int u = 0; u < 4; u++) g_A[(size_t)i * NN + t + 256 * u] = vals[u] * inv;
}

// ---------------- Kernel 2: pairwise MLP via tf32 mma.sync ----------------
// One block per (b, i); 8 warps; each warp processes 8 tiles of 16 j's.
// Layer 2 (32x32, 93% of the FMAs) runs on the tensor pipe with W2 B-fragments
// register-resident. Layer 1 + epilogue tanh on MUFU, fragment-layout-direct.
__global__ __launch_bounds__(256, 2) void agg_kernel(
    const float* __restrict__ x,
    const float* __restrict__ W1, const float* __restrict__ b1,
    const float* __restrict__ W2, const float* __restrict__ b2,
    const float* __restrict__ W3, const float* __restrict__ b3,
    float* __restrict__ out) {
    __shared__ float sA[NN];    // adjacency row A[i][:]
    __shared__ float sX[NN];    // x[b][:]
    __shared__ float sc0[HH];   // (W1[k][0]-W1[k][2])*xi + b1[k]
    __shared__ float sw12[HH];  // W1[k][1]+W1[k][2]
    __shared__ float warpsum[8];

    int t = threadIdx.x;
    int lane = t & 31, warp = t >> 5;
    int g = lane >> 2;   // groupID (row within fragments)
    int q = lane & 3;    // threadID_in_group (col within fragments)
    int bi = blockIdx.x;
    int b = bi >> 10;
    int i = bi & (NN - 1);
    const float* xb = x + b * NN;
    float xi = xb[i];

    for (int idx = t; idx < NN; idx += 256) {
        sA[idx] = g_A[(size_t)i * NN + idx];
        sX[idx] = xb[idx];
    }
    if (t < HH) {
        float w0 = W1[3 * t + 0];
        float w1v = W1[3 * t + 1];
        float w2v = W1[3 * t + 2];
        sc0[t] = fmaf(w0 - w2v, xi, b1[t]);
        sw12[t] = w1v + w2v;
    }

    // --- kernel-lifetime register fragments (uniform across blocks) ---
    // B-frag: B[k][n] = W2[n][k];  b0=(k=kt*8+q, n=nt*8+g), b1=(k+4, n)
    unsigned rb0[4][4], rb1[4][4];
#pragma unroll
    for (int kt = 0; kt < 4; kt++)
#pragma unroll
        for (int nt = 0; nt < 4; nt++) {
            const float* wrow = W2 + (nt * 8 + g) * HH + kt * 8 + q;
            rb0[kt][nt] = tf32(wrow[0]);
            rb1[kt][nt] = tf32(wrow[4]);
        }
    // Epilogue constants for this lane's D columns: m = nt*8 + 2q, 2q+1
    float rw3a[4], rw3b[4], rb2a[4], rb2b[4];
#pragma unroll
    for (int nt = 0; nt < 4; nt++) {
        int m0 = nt * 8 + 2 * q;
        rw3a[nt] = W3[m0];
        rw3b[nt] = W3[m0 + 1];
        rb2a[nt] = b2[m0];
        rb2b[nt] = b2[m0 + 1];
    }
    float b3v = b3[0];
    __syncthreads();

    // Layer-1 constants for this lane's A columns: k = kt*8 + q, kt*8 + q + 4
    float rc0a[4], rc0b[4], rwa[4], rwb[4];
#pragma unroll
    for (int kt = 0; kt < 4; kt++) {
        rc0a[kt] = sc0[kt * 8 + q];
        rc0b[kt] = sc0[kt * 8 + q + 4];
        rwa[kt] = sw12[kt * 8 + q];
        rwb[kt] = sw12[kt * 8 + q + 4];
    }

    float acc = 0.f;
    bool lead = (q == 0);

#pragma unroll
    for (int tile = 0; tile < 8; tile++) {
        int jb = (tile * 8 + warp) * 16;
        float xj1 = sX[jb + g];
        float xj2 = sX[jb + g + 8];

        // D accumulators, initialized with b2 (per-column bias)
        float d[4][4];
#pragma unroll
        for (int nt = 0; nt < 4; nt++) {
            d[nt][0] = rb2a[nt];
            d[nt][1] = rb2b[nt];
            d[nt][2] = rb2a[nt];
            d[nt][3] = rb2b[nt];
        }

        // Layer 1 (fragment-direct) + layer-2 MMAs
#pragma unroll
        for (int kt = 0; kt < 4; kt++) {
            unsigned a0 = tf32(tanhx(fmaf(rwa[kt], xj1, rc0a[kt])));
            unsigned a1 = tf32(tanhx(fmaf(rwa[kt], xj2, rc0a[kt])));
            unsigned a2 = tf32(tanhx(fmaf(rwb[kt], xj1, rc0b[kt])));
            unsigned a3 = tf32(tanhx(fmaf(rwb[kt], xj2, rc0b[kt])));
#pragma unroll
            for (int nt = 0; nt < 4; nt++)
                mma_tf32(d[nt][0], d[nt][1], d[nt][2], d[nt][3],
                         a0, a1, a2, a3, rb0[kt][nt], rb1[kt][nt]);
        }

        // Epilogue: raw[j] = b3 + sum_m W3[m] * tanh(preact[j][m])
        float p1 = 0.f, p2 = 0.f;
#pragma unroll
        for (int nt = 0; nt < 4; nt++) {
            p1 = fmaf(rw3a[nt], tanhx(d[nt][0]), p1);
            p1 = fmaf(rw3b[nt], tanhx(d[nt][1]), p1);
            p2 = fmaf(rw3a[nt], tanhx(d[nt][2]), p2);
            p2 = fmaf(rw3b[nt], tanhx(d[nt][3]), p2);
        }
        // reduce across the 4 lanes of the quad (each holds 8 of 32 m's)
        p1 += __shfl_xor_sync(0xffffffffu, p1, 1);
        p1 += __shfl_xor_sync(0xffffffffu, p1, 2);
        p2 += __shfl_xor_sync(0xffffffffu, p2, 1);
        p2 += __shfl_xor_sync(0xffffffffu, p2, 2);

        // alpha = 2*sigmoid(raw) = 1 + tanh(raw/2)
        float al1 = 1.f + tanhx(0.5f * (p1 + b3v));
        float al2 = 1.f + tanhx(0.5f * (p2 + b3v));

        int j1 = jb + g, j2 = jb + g + 8;
        float c = sA[j1] * al1 * (xj1 - xi) + sA[j2] * al2 * (xj2 - xi);
        acc += lead ? c : 0.f;   // only one lane per quad contributes
    }

    // block reduction over 256 threads
#pragma unroll
    for (int o = 16; o; o >>= 1) acc += __shfl_xor_sync(0xffffffffu, acc, o);
    if (lane == 0) warpsum[warp] = acc;
    __syncthreads();
    if (t == 0) {
        float s = 0.f;
#pragma unroll
        for (int w = 0; w < 8; w++) s += warpsum[w];
        out[b * NN + i] = fmaf(0.1f, s, xi);
    }
}

extern "C" void kernel_launch(void* const* d_in, const int* in_sizes, int n_in,
                              void* d_out, int out_size) {
    (void)in_sizes; (void)n_in; (void)out_size;
    const float* x  = (const float*)d_in[0];
    const float* Th = (const float*)d_in[1];
    const float* W1 = (const float*)d_in[2];
    const float* b1 = (const float*)d_in[3];
    const float* W2 = (const float*)d_in[4];
    const float* b2 = (const float*)d_in[5];
    const float* W3 = (const float*)d_in[6];
    const float* b3 = (const float*)d_in[7];
    float* out = (float*)d_out;

    softmax_kernel<<<NN, 256>>>(Th);
    agg_kernel<<<BB * NN, 256>>>(x, W1, b1, W2, b2, W3, b3, out);
}

// round 4
// speedup vs baseline: 3.4581x; 1.1752x over previous
#include <cuda_runtime.h>

#define NN 1024
#define BB 4
#define HH 32

// 4 MB scratch for the normalized, diagonal-masked softmax adjacency.
__device__ float g_A[NN * NN];

static __device__ __forceinline__ float tanhx(float x) {
    float y;
    asm("tanh.approx.f32 %0, %1;" : "=f"(y) : "f"(x));
    return y;
}
// D += A(m16k8, tf32) * B(k8n8, tf32), fp32 accumulate.
// Operands are raw f32 bit patterns: HMMA.tf32 ignores the low mantissa bits
// (truncation instead of cvt.rna; error well under tolerance).
static __device__ __forceinline__ void mma_tf32(
    float& d0, float& d1, float& d2, float& d3,
    float a0, float a1, float a2, float a3,
    unsigned b0, unsigned b1) {
    asm("mma.sync.aligned.m16n8k8.row.col.f32.tf32.tf32.f32 "
        "{%0,%1,%2,%3},{%4,%5,%6,%7},{%8,%9},{%0,%1,%2,%3};"
        : "+f"(d0), "+f"(d1), "+f"(d2), "+f"(d3)
        : "r"(__float_as_uint(a0)), "r"(__float_as_uint(a1)),
          "r"(__float_as_uint(a2)), "r"(__float_as_uint(a3)),
          "r"(b0), "r"(b1));
}

// ---------------- Kernel 1: masked row softmax of Theta -> g_A ----------------
__global__ __launch_bounds__(256) void softmax_kernel(const float* __restrict__ Theta) {
    int i = blockIdx.x;
    int t = threadIdx.x;
    const float* row = Theta + (size_t)i * NN;

    float vals[4];
    float m = -3.4e38f;
#pragma unroll
    for (int u = 0; u < 4; u++) {
        vals[u] = row[t + 256 * u];
        m = fmaxf(m, vals[u]);
    }
#pragma unroll
    for (int o = 16; o; o >>= 1) m = fmaxf(m, __shfl_xor_sync(0xffffffffu, m, o));

    __shared__ float redmax[8], redsum[8];
    if ((t & 31) == 0) redmax[t >> 5] = m;
    __syncthreads();
    float m0 = redmax[0];
#pragma unroll
    for (int w = 1; w < 8; w++) m0 = fmaxf(m0, redmax[w]);

    float s = 0.f;
#pragma unroll
    for (int u = 0; u < 4; u++) {
        int j = t + 256 * u;
        float e = __expf(vals[u] - m0);
        if (j == i) e = 0.f;
        vals[u] = e;
        s += e;
    }
#pragma unroll
    for (int o = 16; o; o >>= 1) s += __shfl_xor_sync(0xffffffffu, s, o);
    if ((t & 31) == 0) redsum[t >> 5] = s;
    __syncthreads();
    float tot = 0.f;
#pragma unroll
    for (int w = 0; w < 8; w++) tot += redsum[w];
    float inv = 1.0f / tot;
#pragma unroll
    for (int u = 0; u < 4; u++) g_A[(size_t)i * NN + t + 256 * u] = vals[u] * inv;
}

// ---------------- Kernel 2: pairwise MLP via tf32 mma.sync ----------------
// One block per (b, i); 8 warps; each warp does 8 tiles of 16 j's.
// W2 B-fragments and epilogue constants live in smem (fragment order) to cut
// register pressure to <=84 -> 3 blocks/SM (6 warps/SMSP) feeding MUFU.
__global__ __launch_bounds__(256, 3) void agg_kernel(
    const float* __restrict__ x,
    const float* __restrict__ W1, const float* __restrict__ b1,
    const float* __restrict__ W2, const float* __restrict__ b2,
    const float* __restrict__ W3, const float* __restrict__ b3,
    float* __restrict__ out) {
    __shared__ float sA[NN];           // adjacency row A[i][:]
    __shared__ float sX[NN];           // x[b][:]
    __shared__ float sc0[HH];          // (W1[k][0]-W1[k][2])*xi + b1[k]
    __shared__ float sw12[HH];         // W1[k][1]+W1[k][2]
    __shared__ float2 sW2f[16][32];    // B-fragments: [(kt*4+nt)][lane] = {B(k,n), B(k+4,n)}
    __shared__ float4 sEp[4][4];       // [nt][q] = {W3[m0], W3[m0+1], b2[m0], b2[m0+1]}
    __shared__ float warpsum[8];

    int t = threadIdx.x;
    int lane = t & 31, warp = t >> 5;
    int g = lane >> 2;   // groupID (row within fragments)
    int q = lane & 3;    // threadID_in_group
    int bi = blockIdx.x;
    int b = bi >> 10;
    int i = bi & (NN - 1);
    const float* xb = x + b * NN;
    float xi = xb[i];

    for (int idx = t; idx < NN; idx += 256) {
        sA[idx] = g_A[(size_t)i * NN + idx];
        sX[idx] = xb[idx];
    }
    // B-fragments in mma layout: b0 = W2[n=nt*8+g][k=kt*8+q], b1 = same k+4
    for (int idx = t; idx < 512; idx += 256) {
        int f = idx >> 5, ln = idx & 31;
        int kt = f >> 2, nt = f & 3;
        int gg = ln >> 2, qq = ln & 3;
        const float* wrow = W2 + (nt * 8 + gg) * HH + kt * 8 + qq;
        sW2f[f][ln] = make_float2(wrow[0], wrow[4]);
    }
    if (t < 16) {
        int nt = t >> 2, qq = t & 3;
        int m0 = nt * 8 + 2 * qq;
        sEp[nt][qq] = make_float4(W3[m0], W3[m0 + 1], b2[m0], b2[m0 + 1]);
    }
    if (t < HH) {
        float w0 = W1[3 * t + 0];
        float w1v = W1[3 * t + 1];
        float w2v = W1[3 * t + 2];
        sc0[t] = fmaf(w0 - w2v, xi, b1[t]);
        sw12[t] = w1v + w2v;
    }
    float b3v = b3[0];
    __syncthreads();

    // Layer-1 constants for this lane's A columns: k = kt*8 + q, kt*8 + q + 4
    float rc0a[4], rc0b[4], rwa[4], rwb[4];
#pragma unroll
    for (int kt = 0; kt < 4; kt++) {
        rc0a[kt] = sc0[kt * 8 + q];
        rc0b[kt] = sc0[kt * 8 + q + 4];
        rwa[kt] = sw12[kt * 8 + q];
        rwb[kt] = sw12[kt * 8 + q + 4];
    }

    float acc = 0.f;
    bool lead = (q == 0);

#pragma unroll
    for (int tile = 0; tile < 8; tile++) {
        int jb = (tile * 8 + warp) * 16;
        float xj1 = sX[jb + g];
        float xj2 = sX[jb + g + 8];

        float d[4][4];
#pragma unroll
        for (int nt = 0; nt < 4; nt++)
            d[nt][0] = d[nt][1] = d[nt][2] = d[nt][3] = 0.f;

        // Layer 1 (fragment-direct, raw-f32 tf32 operands) + layer-2 MMAs
#pragma unroll
        for (int kt = 0; kt < 4; kt++) {
            float a0 = tanhx(fmaf(rwa[kt], xj1, rc0a[kt]));
            float a1 = tanhx(fmaf(rwa[kt], xj2, rc0a[kt]));
            float a2 = tanhx(fmaf(rwb[kt], xj1, rc0b[kt]));
            float a3 = tanhx(fmaf(rwb[kt], xj2, rc0b[kt]));
#pragma unroll
            for (int nt = 0; nt < 4; nt++) {
                float2 wf = sW2f[kt * 4 + nt][lane];  // LDS.64, conflict-free
                mma_tf32(d[nt][0], d[nt][1], d[nt][2], d[nt][3],
                         a0, a1, a2, a3,
                         __float_as_uint(wf.x), __float_as_uint(wf.y));
            }
        }

        // Epilogue: raw[j] = b3 + sum_m W3[m] * tanh(preact[j][m] + b2[m])
        float p1 = 0.f, p2 = 0.f;
#pragma unroll
        for (int nt = 0; nt < 4; nt++) {
            float4 ep = sEp[nt][q];  // {w3a, w3b, b2a, b2b}, broadcast by q
            p1 = fmaf(ep.x, tanhx(d[nt][0] + ep.z), p1);
            p1 = fmaf(ep.y, tanhx(d[nt][1] + ep.w), p1);
            p2 = fmaf(ep.x, tanhx(d[nt][2] + ep.z), p2);
            p2 = fmaf(ep.y, tanhx(d[nt][3] + ep.w), p2);
        }
        // reduce across the 4 lanes of the quad (each holds 8 of 32 m's)
        p1 += __shfl_xor_sync(0xffffffffu, p1, 1);
        p1 += __shfl_xor_sync(0xffffffffu, p1, 2);
        p2 += __shfl_xor_sync(0xffffffffu, p2, 1);
        p2 += __shfl_xor_sync(0xffffffffu, p2, 2);

        // alpha = 2*sigmoid(raw) = 1 + tanh(raw/2)
        float al1 = 1.f + tanhx(0.5f * (p1 + b3v));
        float al2 = 1.f + tanhx(0.5f * (p2 + b3v));

        int j1 = jb + g, j2 = jb + g + 8;
        float c = sA[j1] * al1 * (xj1 - xi) + sA[j2] * al2 * (xj2 - xi);
        acc += lead ? c : 0.f;   // one lane per quad contributes
    }

    // block reduction over 256 threads
#pragma unroll
    for (int o = 16; o; o >>= 1) acc += __shfl_xor_sync(0xffffffffu, acc, o);
    if (lane == 0) warpsum[warp] = acc;
    __syncthreads();
    if (t == 0) {
        float s = 0.f;
#pragma unroll
        for (int w = 0; w < 8; w++) s += warpsum[w];
        out[b * NN + i] = fmaf(0.1f, s, xi);
    }
}

extern "C" void kernel_launch(void* const* d_in, const int* in_sizes, int n_in,
                              void* d_out, int out_size) {
    (void)in_sizes; (void)n_in; (void)out_size;
    const float* x  = (const float*)d_in[0];
    const float* Th = (const float*)d_in[1];
    const float* W1 = (const float*)d_in[2];
    const float* b1 = (const float*)d_in[3];
    const float* W2 = (const float*)d_in[4];
    const float* b2 = (const float*)d_in[5];
    const float* W3 = (const float*)d_in[6];
    const float* b3 = (const float*)d_in[7];
    float* out = (float*)d_out;

    softmax_kernel<<<NN, 256>>>(Th);
    agg_kernel<<<BB * NN, 256>>>(x, W1, b1, W2, b2, W3, b3, out);
}

// round 5
// speedup vs baseline: 3.5349x; 1.0222x over previous
#include <cuda_runtime.h>

#define NN 1024
#define BB 4
#define HH 32

// 4 MB scratch for the normalized, diagonal-masked softmax adjacency.
__device__ float g_A[NN * NN];

// ---------------- f16x2 helpers ----------------
static __device__ __forceinline__ unsigned packh2(float lo, float hi) {
    unsigned r;  // first PTX source -> upper half
    asm("cvt.rn.f16x2.f32 %0, %1, %2;" : "=r"(r) : "f"(hi), "f"(lo));
    return r;
}
static __device__ __forceinline__ unsigned tanh_h2(unsigned v) {
    unsigned r;
    asm("tanh.approx.f16x2 %0, %1;" : "=r"(r) : "r"(v));
    return r;
}
static __device__ __forceinline__ unsigned hfma2(unsigned a, unsigned b, unsigned c) {
    unsigned d;
    asm("fma.rn.f16x2 %0, %1, %2, %3;" : "=r"(d) : "r"(a), "r"(b), "r"(c));
    return d;
}
static __device__ __forceinline__ float hlo(unsigned v) {
    float f;
    asm("{.reg .f16 l,h; mov.b32 {l,h}, %1; cvt.f32.f16 %0, l;}" : "=f"(f) : "r"(v));
    return f;
}
static __device__ __forceinline__ float hhi(unsigned v) {
    float f;
    asm("{.reg .f16 l,h; mov.b32 {l,h}, %1; cvt.f32.f16 %0, h;}" : "=f"(f) : "r"(v));
    return f;
}
static __device__ __forceinline__ float tanhx(float x) {
    float y;
    asm("tanh.approx.f32 %0, %1;" : "=f"(y) : "f"(x));
    return y;
}
// D += A(m16k16 f16) * B(k16n8 f16), fp32 accumulate.
static __device__ __forceinline__ void mma_f16(
    float& d0, float& d1, float& d2, float& d3,
    unsigned a0, unsigned a1, unsigned a2, unsigned a3,
    unsigned b0, unsigned b1) {
    asm("mma.sync.aligned.m16n8k16.row.col.f32.f16.f16.f32 "
        "{%0,%1,%2,%3},{%4,%5,%6,%7},{%8,%9},{%0,%1,%2,%3};"
        : "+f"(d0), "+f"(d1), "+f"(d2), "+f"(d3)
        : "r"(a0), "r"(a1), "r"(a2), "r"(a3), "r"(b0), "r"(b1));
}

// ---------------- Kernel 1: masked row softmax of Theta -> g_A ----------------
__global__ __launch_bounds__(256) void softmax_kernel(const float* __restrict__ Theta) {
    int i = blockIdx.x;
    int t = threadIdx.x;
    const float* row = Theta + (size_t)i * NN;

    float vals[4];
    float m = -3.4e38f;
#pragma unroll
    for (int u = 0; u < 4; u++) {
        vals[u] = row[t + 256 * u];
        m = fmaxf(m, vals[u]);
    }
#pragma unroll
    for (int o = 16; o; o >>= 1) m = fmaxf(m, __shfl_xor_sync(0xffffffffu, m, o));

    __shared__ float redmax[8], redsum[8];
    if ((t & 31) == 0) redmax[t >> 5] = m;
    __syncthreads();
    float m0 = redmax[0];
#pragma unroll
    for (int w = 1; w < 8; w++) m0 = fmaxf(m0, redmax[w]);

    float s = 0.f;
#pragma unroll
    for (int u = 0; u < 4; u++) {
        int j = t + 256 * u;
        float e = __expf(vals[u] - m0);
        if (j == i) e = 0.f;
        vals[u] = e;
        s += e;
    }
#pragma unroll
    for (int o = 16; o; o >>= 1) s += __shfl_xor_sync(0xffffffffu, s, o);
    if ((t & 31) == 0) redsum[t >> 5] = s;
    __syncthreads();
    float tot = 0.f;
#pragma unroll
    for (int w = 0; w < 8; w++) tot += redsum[w];
    float inv = 1.0f / tot;
#pragma unroll
    for (int u = 0; u < 4; u++) g_A[(size_t)i * NN + t + 256 * u] = vals[u] * inv;
}

// ---------------- Kernel 2: pairwise MLP via f16 mma + f16x2 tanh ----------------
// One block per (b, i); 8 warps; 8 tiles of 16 j's per warp.
// All tanh on MUFU as f16x2 (2 per op); layer 2 = m16n8k16 f16 HMMA with W2
// register-resident as f16x2 fragments; layer 1 preacts via HFMA2.
__global__ __launch_bounds__(256, 3) void agg_kernel(
    const float* __restrict__ x,
    const float* __restrict__ W1, const float* __restrict__ b1,
    const float* __restrict__ W2, const float* __restrict__ b2,
    const float* __restrict__ W3, const float* __restrict__ b3,
    float* __restrict__ out) {
    __shared__ float sA[NN];           // adjacency row A[i][:]
    __shared__ float sX[NN];           // x[b][:]
    __shared__ float sc0[HH];          // (W1[k][0]-W1[k][2])*xi + b1[k]
    __shared__ float sw12[HH];         // W1[k][1]+W1[k][2]
    __shared__ float4 sEp[4][4];       // [nt][q] = {b2[m0], b2[m0+1], W3h2-as-float, 0}
    __shared__ float warpsum[8];

    int t = threadIdx.x;
    int lane = t & 31, warp = t >> 5;
    int g = lane >> 2;   // groupID
    int q = lane & 3;    // threadID_in_group
    int bi = blockIdx.x;
    int b = bi >> 10;
    int i = bi & (NN - 1);
    const float* xb = x + b * NN;
    float xi = xb[i];

    for (int idx = t; idx < NN; idx += 256) {
        sA[idx] = g_A[(size_t)i * NN + idx];
        sX[idx] = xb[idx];
    }
    if (t < 16) {
        int nt = t >> 2, qq = t & 3;
        int m0 = nt * 8 + 2 * qq;
        unsigned w3h = packh2(W3[m0], W3[m0 + 1]);
        sEp[nt][qq] = make_float4(b2[m0], b2[m0 + 1], __uint_as_float(w3h), 0.f);
    }
    if (t < HH) {
        float w0 = W1[3 * t + 0];
        float w1v = W1[3 * t + 1];
        float w2v = W1[3 * t + 2];
        sc0[t] = fmaf(w0 - w2v, xi, b1[t]);
        sw12[t] = w1v + w2v;
    }
    float b3v = b3[0];

    // W2 B-fragments register-resident (f16x2), m16n8k16 col-major B layout:
    // rB[kt][nt][0] = {W2[n][k0], W2[n][k0+1]}, rB[..][1] = {W2[n][k0+8], W2[n][k0+9]}
    // with n = nt*8+g, k0 = kt*16+2q.
    unsigned rB[2][4][2];
#pragma unroll
    for (int kt = 0; kt < 2; kt++)
#pragma unroll
        for (int nt = 0; nt < 4; nt++) {
            const float* wrow = W2 + (nt * 8 + g) * HH + kt * 16 + 2 * q;
            rB[kt][nt][0] = packh2(wrow[0], wrow[1]);
            rB[kt][nt][1] = packh2(wrow[8], wrow[9]);
        }
    __syncthreads();

    // Layer-1 packed constants for this lane's 4 k-pairs: k0(p) = 2q + 8p
    unsigned c0h[4], w12h[4];
#pragma unroll
    for (int p = 0; p < 4; p++) {
        int k0 = 2 * q + 8 * p;
        c0h[p] = packh2(sc0[k0], sc0[k0 + 1]);
        w12h[p] = packh2(sw12[k0], sw12[k0 + 1]);
    }

    float acc = 0.f;
    bool lead = (q == 0);

#pragma unroll
    for (int tile = 0; tile < 8; tile++) {
        int jb = (tile * 8 + warp) * 16;
        float xj1 = sX[jb + g];
        float xj2 = sX[jb + g + 8];
        unsigned xh1 = packh2(xj1, xj1);
        unsigned xh2 = packh2(xj2, xj2);

        // Layer 1: A-fragments directly (aG = row g, aH = row g+8)
        unsigned aG[4], aH[4];
#pragma unroll
        for (int p = 0; p < 4; p++) {
            aG[p] = tanh_h2(hfma2(w12h[p], xh1, c0h[p]));
            aH[p] = tanh_h2(hfma2(w12h[p], xh2, c0h[p]));
        }

        float d[4][4];
#pragma unroll
        for (int nt = 0; nt < 4; nt++)
            d[nt][0] = d[nt][1] = d[nt][2] = d[nt][3] = 0.f;

#pragma unroll
        for (int nt = 0; nt < 4; nt++)
            mma_f16(d[nt][0], d[nt][1], d[nt][2], d[nt][3],
                    aG[0], aH[0], aG[1], aH[1], rB[0][nt][0], rB[0][nt][1]);
#pragma unroll
        for (int nt = 0; nt < 4; nt++)
            mma_f16(d[nt][0], d[nt][1], d[nt][2], d[nt][3],
                    aG[2], aH[2], aG[3], aH[3], rB[1][nt][0], rB[1][nt][1]);

        // Epilogue: raw[j] = b3 + sum_m W3[m]*tanh(d + b2), f16x2 pairs over m
        unsigned p1h = 0u, p2h = 0u;
#pragma unroll
        for (int nt = 0; nt < 4; nt++) {
            float4 ep = sEp[nt][q];  // LDS.128 broadcast within quad
            unsigned th1 = tanh_h2(packh2(d[nt][0] + ep.x, d[nt][1] + ep.y));
            unsigned th2 = tanh_h2(packh2(d[nt][2] + ep.x, d[nt][3] + ep.y));
            unsigned w3h = __float_as_uint(ep.z);
            p1h = hfma2(w3h, th1, p1h);
            p2h = hfma2(w3h, th2, p2h);
        }
        float p1 = hlo(p1h) + hhi(p1h);
        float p2 = hlo(p2h) + hhi(p2h);
        // reduce across the 4 lanes of the quad (each holds 8 of 32 m's)
        p1 += __shfl_xor_sync(0xffffffffu, p1, 1);
        p1 += __shfl_xor_sync(0xffffffffu, p1, 2);
        p2 += __shfl_xor_sync(0xffffffffu, p2, 1);
        p2 += __shfl_xor_sync(0xffffffffu, p2, 2);

        // alpha = 2*sigmoid(raw) = 1 + tanh(raw/2); both alphas in one f16x2 tanh
        unsigned ah = tanh_h2(packh2(0.5f * (p1 + b3v), 0.5f * (p2 + b3v)));
        float al1 = 1.f + hlo(ah);
        float al2 = 1.f + hhi(ah);

        int j1 = jb + g, j2 = jb + g + 8;
        float c = sA[j1] * al1 * (xj1 - xi) + sA[j2] * al2 * (xj2 - xi);
        acc += lead ? c : 0.f;   // one lane per quad contributes
    }

    // block reduction over 256 threads
#pragma unroll
    for (int o = 16; o; o >>= 1) acc += __shfl_xor_sync(0xffffffffu, acc, o);
    if (lane == 0) warpsum[warp] = acc;
    __syncthreads();
    if (t == 0) {
        float s = 0.f;
#pragma unroll
        for (int w = 0; w < 8; w++) s += warpsum[w];
        out[b * NN + i] = fmaf(0.1f, s, xi);
    }
}

extern "C" void kernel_launch(void* const* d_in, const int* in_sizes, int n_in,
                              void* d_out, int out_size) {
    (void)in_sizes; (void)n_in; (void)out_size;
    const float* x  = (const float*)d_in[0];
    const float* Th = (const float*)d_in[1];
    const float* W1 = (const float*)d_in[2];
    const float* b1 = (const float*)d_in[3];
    const float* W2 = (const float*)d_in[4];
    const float* b2 = (const float*)d_in[5];
    const float* W3 = (const float*)d_in[6];
    const float* b3 = (const float*)d_in[7];
    float* out = (float*)d_out;

    softmax_kernel<<<NN, 256>>>(Th);
    agg_kernel<<<BB * NN, 256>>>(x, W1, b1, W2, b2, W3, b3, out);
}

// round 6
// speedup vs baseline: 3.5361x; 1.0003x over previous
#include <cuda_runtime.h>

#define NN 1024
#define BB 4
#define HH 32

// 4 MB scratch for the normalized, diagonal-masked softmax adjacency.
__device__ float g_A[NN * NN];

// ---------------- f16x2 helpers ----------------
static __device__ __forceinline__ unsigned packh2(float lo, float hi) {
    unsigned r;  // first PTX source -> upper half
    asm("cvt.rn.f16x2.f32 %0, %1, %2;" : "=r"(r) : "f"(hi), "f"(lo));
    return r;
}
static __device__ __forceinline__ unsigned tanh_h2(unsigned v) {
    unsigned r;
    asm("tanh.approx.f16x2 %0, %1;" : "=r"(r) : "r"(v));
    return r;
}
static __device__ __forceinline__ unsigned hfma2(unsigned a, unsigned b, unsigned c) {
    unsigned d;
    asm("fma.rn.f16x2 %0, %1, %2, %3;" : "=r"(d) : "r"(a), "r"(b), "r"(c));
    return d;
}
static __device__ __forceinline__ float hlo(unsigned v) {
    float f;
    asm("{.reg .f16 l,h; mov.b32 {l,h}, %1; cvt.f32.f16 %0, l;}" : "=f"(f) : "r"(v));
    return f;
}
static __device__ __forceinline__ float hhi(unsigned v) {
    float f;
    asm("{.reg .f16 l,h; mov.b32 {l,h}, %1; cvt.f32.f16 %0, h;}" : "=f"(f) : "r"(v));
    return f;
}
// D += A(m16k16 f16) * B(k16n8 f16), fp32 accumulate.
static __device__ __forceinline__ void mma_f16(
    float& d0, float& d1, float& d2, float& d3,
    unsigned a0, unsigned a1, unsigned a2, unsigned a3,
    unsigned b0, unsigned b1) {
    asm("mma.sync.aligned.m16n8k16.row.col.f32.f16.f16.f32 "
        "{%0,%1,%2,%3},{%4,%5,%6,%7},{%8,%9},{%0,%1,%2,%3};"
        : "+f"(d0), "+f"(d1), "+f"(d2), "+f"(d3)
        : "r"(a0), "r"(a1), "r"(a2), "r"(a3), "r"(b0), "r"(b1));
}

// ---------------- Kernel 1: masked row softmax of Theta -> g_A ----------------
__global__ __launch_bounds__(256) void softmax_kernel(const float* __restrict__ Theta) {
    int i = blockIdx.x;
    int t = threadIdx.x;
    const float* row = Theta + (size_t)i * NN;

    float vals[4];
    float m = -3.4e38f;
#pragma unroll
    for (int u = 0; u < 4; u++) {
        vals[u] = row[t + 256 * u];
        m = fmaxf(m, vals[u]);
    }
#pragma unroll
    for (int o = 16; o; o >>= 1) m = fmaxf(m, __shfl_xor_sync(0xffffffffu, m, o));

    __shared__ float redmax[8], redsum[8];
    if ((t & 31) == 0) redmax[t >> 5] = m;
    __syncthreads();
    float m0 = redmax[0];
#pragma unroll
    for (int w = 1; w < 8; w++) m0 = fmaxf(m0, redmax[w]);

    float s = 0.f;
#pragma unroll
    for (int u = 0; u < 4; u++) {
        int j = t + 256 * u;
        float e = __expf(vals[u] - m0);
        if (j == i) e = 0.f;
        vals[u] = e;
        s += e;
    }
#pragma unroll
    for (int o = 16; o; o >>= 1) s += __shfl_xor_sync(0xffffffffu, s, o);
    if ((t & 31) == 0) redsum[t >> 5] = s;
    __syncthreads();
    float tot = 0.f;
#pragma unroll
    for (int w = 0; w < 8; w++) tot += redsum[w];
    float inv = 1.0f / tot;
#pragma unroll
    for (int u = 0; u < 4; u++) g_A[(size_t)i * NN + t + 256 * u] = vals[u] * inv;
}

// ---------------- Kernel 2: pairwise MLP, layers 2 AND 3 on tensor pipe ----------------
// One block per (b, i); 8 warps; 8 tiles of 16 j's per warp.
// Layer 2: m16n8k16 f16 HMMA, W2 register-resident, accumulators seeded with b2.
// Layer 3: two more HMMAs against a W3 B-fragment (col 0 = W3) -> raw lands in
// the q==0 lanes' col-0 accumulators. No shuffle reduction, no HFMA2 epilogue.
__global__ __launch_bounds__(256, 3) void agg_kernel(
    const float* __restrict__ x,
    const float* __restrict__ W1, const float* __restrict__ b1,
    const float* __restrict__ W2, const float* __restrict__ b2,
    const float* __restrict__ W3, const float* __restrict__ b3,
    float* __restrict__ out) {
    __shared__ float sA[NN];           // adjacency row A[i][:]
    __shared__ float sX[NN];           // x[b][:]
    __shared__ unsigned sXh[NN];       // x pre-packed f16x2 {x,x}
    __shared__ float sc0[HH];          // (W1[k][0]-W1[k][2])*xi + b1[k]
    __shared__ float sw12[HH];         // W1[k][1]+W1[k][2]
    __shared__ float warpsum[8];

    int t = threadIdx.x;
    int lane = t & 31, warp = t >> 5;
    int g = lane >> 2;   // groupID
    int q = lane & 3;    // threadID_in_group
    int bi = blockIdx.x;
    int b = bi >> 10;
    int i = bi & (NN - 1);
    const float* xb = x + b * NN;
    float xi = xb[i];

    for (int idx = t; idx < NN; idx += 256) {
        float v = xb[idx];
        sA[idx] = g_A[(size_t)i * NN + idx];
        sX[idx] = v;
        sXh[idx] = packh2(v, v);
    }
    if (t < HH) {
        float w0 = W1[3 * t + 0];
        float w1v = W1[3 * t + 1];
        float w2v = W1[3 * t + 2];
        sc0[t] = fmaf(w0 - w2v, xi, b1[t]);
        sw12[t] = w1v + w2v;
    }
    float b3v = b3[0];

    // W2 B-fragments register-resident (f16x2), m16n8k16 col-major B layout.
    unsigned rB[2][4][2];
#pragma unroll
    for (int kt = 0; kt < 2; kt++)
#pragma unroll
        for (int nt = 0; nt < 4; nt++) {
            const float* wrow = W2 + (nt * 8 + g) * HH + kt * 16 + 2 * q;
            rB[kt][nt][0] = packh2(wrow[0], wrow[1]);
            rB[kt][nt][1] = packh2(wrow[8], wrow[9]);
        }
    // b2 seed values for this lane's accumulator columns m = nt*8+2q, +1
    float rb2a[4], rb2b[4];
#pragma unroll
    for (int nt = 0; nt < 4; nt++) {
        rb2a[nt] = b2[nt * 8 + 2 * q];
        rb2b[nt] = b2[nt * 8 + 2 * q + 1];
    }
    // Layer-3 B-fragment over k=m(hidden): column n=0 carries W3, others zero.
    // Thread (g,q): b0 = {B[2q][g], B[2q+1][g]}, b1 = {B[2q+8][g], B[2q+9][g]}.
    unsigned rW3[2][2];
    if (g == 0) {
        rW3[0][0] = packh2(W3[2 * q], W3[2 * q + 1]);
        rW3[0][1] = packh2(W3[2 * q + 8], W3[2 * q + 9]);
        rW3[1][0] = packh2(W3[2 * q + 16], W3[2 * q + 17]);
        rW3[1][1] = packh2(W3[2 * q + 24], W3[2 * q + 25]);
    } else {
        rW3[0][0] = rW3[0][1] = rW3[1][0] = rW3[1][1] = 0u;
    }
    __syncthreads();

    // Layer-1 packed constants for this lane's 4 k-pairs: k0(p) = 2q + 8p
    unsigned c0h[4], w12h[4];
#pragma unroll
    for (int p = 0; p < 4; p++) {
        int k0 = 2 * q + 8 * p;
        c0h[p] = packh2(sc0[k0], sc0[k0 + 1]);
        w12h[p] = packh2(sw12[k0], sw12[k0 + 1]);
    }

    float acc = 0.f;
    bool lead = (q == 0);

#pragma unroll
    for (int tile = 0; tile < 8; tile++) {
        int jb = (tile * 8 + warp) * 16;
        unsigned xh1 = sXh[jb + g];
        unsigned xh2 = sXh[jb + g + 8];

        // Layer 1: A-fragments directly (aG = row g, aH = row g+8)
        unsigned aG[4], aH[4];
#pragma unroll
        for (int p = 0; p < 4; p++) {
            aG[p] = tanh_h2(hfma2(w12h[p], xh1, c0h[p]));
            aH[p] = tanh_h2(hfma2(w12h[p], xh2, c0h[p]));
        }

        // Layer 2: accumulators seeded with b2
        float d[4][4];
#pragma unroll
        for (int nt = 0; nt < 4; nt++) {
            d[nt][0] = rb2a[nt];
            d[nt][1] = rb2b[nt];
            d[nt][2] = rb2a[nt];
            d[nt][3] = rb2b[nt];
        }
#pragma unroll
        for (int nt = 0; nt < 4; nt++)
            mma_f16(d[nt][0], d[nt][1], d[nt][2], d[nt][3],
                    aG[0], aH[0], aG[1], aH[1], rB[0][nt][0], rB[0][nt][1]);
#pragma unroll
        for (int nt = 0; nt < 4; nt++)
            mma_f16(d[nt][0], d[nt][1], d[nt][2], d[nt][3],
                    aG[2], aH[2], aG[3], aH[3], rB[1][nt][0], rB[1][nt][1]);

        // tanh of layer-2 preacts; pairs are already layer-3 A-fragments
        unsigned th1[4], th2[4];
#pragma unroll
        for (int nt = 0; nt < 4; nt++) {
            th1[nt] = tanh_h2(packh2(d[nt][0], d[nt][1]));  // row g
            th2[nt] = tanh_h2(packh2(d[nt][2], d[nt][3]));  // row g+8
        }

        // Layer 3 via MMA: raw = b3 + sum_m W3[m]*tanh(...) in col 0 (q==0 lanes)
        float r0 = b3v, r1 = b3v, r2 = b3v, r3 = b3v;
        mma_f16(r0, r1, r2, r3, th1[0], th2[0], th1[1], th2[1],
                rW3[0][0], rW3[0][1]);
        mma_f16(r0, r1, r2, r3, th1[2], th2[2], th1[3], th2[3],
                rW3[1][0], rW3[1][1]);

        // alpha = 2*sigmoid(raw) = 1 + tanh(raw/2); both alphas in one f16x2 tanh
        unsigned ah = tanh_h2(packh2(0.5f * r0, 0.5f * r2));
        float al1 = 1.f + hlo(ah);
        float al2 = 1.f + hhi(ah);

        int j1 = jb + g, j2 = jb + g + 8;
        float xj1 = sX[j1], xj2 = sX[j2];
        float c = sA[j1] * al1 * (xj1 - xi) + sA[j2] * al2 * (xj2 - xi);
        acc += lead ? c : 0.f;   // raw is only valid on q==0 lanes
    }

    // block reduction over 256 threads
#pragma unroll
    for (int o = 16; o; o >>= 1) acc += __shfl_xor_sync(0xffffffffu, acc, o);
    if (lane == 0) warpsum[warp] = acc;
    __syncthreads();
    if (t == 0) {
        float s = 0.f;
#pragma unroll
        for (int w = 0; w < 8; w++) s += warpsum[w];
        out[b * NN + i] = fmaf(0.1f, s, xi);
    }
}

extern "C" void kernel_launch(void* const* d_in, const int* in_sizes, int n_in,
                              void* d_out, int out_size) {
    (void)in_sizes; (void)n_in; (void)out_size;
    const float* x  = (const float*)d_in[0];
    const float* Th = (const float*)d_in[1];
    const float* W1 = (const float*)d_in[2];
    const float* b1 = (const float*)d_in[3];
    const float* W2 = (const float*)d_in[4];
    const float* b2 = (const float*)d_in[5];
    const float* W3 = (const float*)d_in[6];
    const float* b3 = (const float*)d_in[7];
    float* out = (float*)d_out;

    softmax_kernel<<<NN, 256>>>(Th);
    agg_kernel<<<BB * NN, 256>>>(x, W1, b1, W2, b2, W3, b3, out);
}

// round 7
// speedup vs baseline: 3.6541x; 1.0334x over previous
#include <cuda_runtime.h>

#define NN 1024
#define BB 4
#define HH 32

// 4 MB scratch for the normalized, diagonal-masked softmax adjacency.
__device__ float g_A[NN * NN];

// ---------------- f16x2 helpers ----------------
static __device__ __forceinline__ unsigned packh2(float lo, float hi) {
    unsigned r;  // first PTX source -> upper half
    asm("cvt.rn.f16x2.f32 %0, %1, %2;" : "=r"(r) : "f"(hi), "f"(lo));
    return r;
}
static __device__ __forceinline__ unsigned tanh_h2(unsigned v) {
    unsigned r;
    asm("tanh.approx.f16x2 %0, %1;" : "=r"(r) : "r"(v));
    return r;
}
static __device__ __forceinline__ unsigned hfma2(unsigned a, unsigned b, unsigned c) {
    unsigned d;
    asm("fma.rn.f16x2 %0, %1, %2, %3;" : "=r"(d) : "r"(a), "r"(b), "r"(c));
    return d;
}
static __device__ __forceinline__ float hlo(unsigned v) {
    float f;
    asm("{.reg .f16 l,h; mov.b32 {l,h}, %1; cvt.f32.f16 %0, l;}" : "=f"(f) : "r"(v));
    return f;
}
static __device__ __forceinline__ float hhi(unsigned v) {
    float f;
    asm("{.reg .f16 l,h; mov.b32 {l,h}, %1; cvt.f32.f16 %0, h;}" : "=f"(f) : "r"(v));
    return f;
}
// D(f16) += A(m16k16 f16) * B(k16n8 f16): C/D packed f16x2 (2 regs).
// d0 = {row g,  cols 2q,2q+1}, d1 = {row g+8, cols 2q,2q+1}.
static __device__ __forceinline__ void mma_f16h(
    unsigned& d0, unsigned& d1,
    unsigned a0, unsigned a1, unsigned a2, unsigned a3,
    unsigned b0, unsigned b1) {
    asm("mma.sync.aligned.m16n8k16.row.col.f16.f16.f16.f16 "
        "{%0,%1},{%2,%3,%4,%5},{%6,%7},{%0,%1};"
        : "+r"(d0), "+r"(d1)
        : "r"(a0), "r"(a1), "r"(a2), "r"(a3), "r"(b0), "r"(b1));
}
// D(f32) += A(m16k16 f16) * B(k16n8 f16), fp32 accumulate.
static __device__ __forceinline__ void mma_f16(
    float& d0, float& d1, float& d2, float& d3,
    unsigned a0, unsigned a1, unsigned a2, unsigned a3,
    unsigned b0, unsigned b1) {
    asm("mma.sync.aligned.m16n8k16.row.col.f32.f16.f16.f32 "
        "{%0,%1,%2,%3},{%4,%5,%6,%7},{%8,%9},{%0,%1,%2,%3};"
        : "+f"(d0), "+f"(d1), "+f"(d2), "+f"(d3)
        : "r"(a0), "r"(a1), "r"(a2), "r"(a3), "r"(b0), "r"(b1));
}

// ---------------- Kernel 1: masked row softmax of Theta -> g_A ----------------
__global__ __launch_bounds__(256) void softmax_kernel(const float* __restrict__ Theta) {
    int i = blockIdx.x;
    int t = threadIdx.x;
    const float* row = Theta + (size_t)i * NN;

    float vals[4];
    float m = -3.4e38f;
#pragma unroll
    for (int u = 0; u < 4; u++) {
        vals[u] = row[t + 256 * u];
        m = fmaxf(m, vals[u]);
    }
#pragma unroll
    for (int o = 16; o; o >>= 1) m = fmaxf(m, __shfl_xor_sync(0xffffffffu, m, o));

    __shared__ float redmax[8], redsum[8];
    if ((t & 31) == 0) redmax[t >> 5] = m;
    __syncthreads();
    float m0 = redmax[0];
#pragma unroll
    for (int w = 1; w < 8; w++) m0 = fmaxf(m0, redmax[w]);

    float s = 0.f;
#pragma unroll
    for (int u = 0; u < 4; u++) {
        int j = t + 256 * u;
        float e = __expf(vals[u] - m0);
        if (j == i) e = 0.f;
        vals[u] = e;
        s += e;
    }
#pragma unroll
    for (int o = 16; o; o >>= 1) s += __shfl_xor_sync(0xffffffffu, s, o);
    if ((t & 31) == 0) redsum[t >> 5] = s;
    __syncthreads();
    float tot = 0.f;
#pragma unroll
    for (int w = 0; w < 8; w++) tot += redsum[w];
    float inv = 1.0f / tot;
#pragma unroll
    for (int u = 0; u < 4; u++) g_A[(size_t)i * NN + t + 256 * u] = vals[u] * inv;
}

// ---------------- Kernel 2: pairwise MLP, all GEMMs on tensor pipe ----------------
// One block per (b, i); 8 warps; 8 tiles of 16 j's per warp.
// Layer 2: f16-accumulator HMMA (D already f16x2-packed -> no cvt packs),
// seeded with packed b2. Layer 3: f32-accum HMMA vs W3-in-col-0 fragment.
// Target <=64 regs -> 4 blocks/SM (32 warps) for latency hiding.
__global__ __launch_bounds__(256, 4) void agg_kernel(
    const float* __restrict__ x,
    const float* __restrict__ W1, const float* __restrict__ b1,
    const float* __restrict__ W2, const float* __restrict__ b2,
    const float* __restrict__ W3, const float* __restrict__ b3,
    float* __restrict__ out) {
    __shared__ float sA[NN];           // adjacency row A[i][:]
    __shared__ float sX[NN];           // x[b][:]
    __shared__ unsigned sXh[NN];       // x pre-packed f16x2 {x,x}
    __shared__ float sc0[HH];          // (W1[k][0]-W1[k][2])*xi + b1[k]
    __shared__ float sw12[HH];         // W1[k][1]+W1[k][2]
    __shared__ float warpsum[8];

    int t = threadIdx.x;
    int lane = t & 31, warp = t >> 5;
    int g = lane >> 2;   // groupID
    int q = lane & 3;    // threadID_in_group
    int bi = blockIdx.x;
    int b = bi >> 10;
    int i = bi & (NN - 1);
    const float* xb = x + b * NN;
    float xi = xb[i];

    for (int idx = t; idx < NN; idx += 256) {
        float v = xb[idx];
        sA[idx] = g_A[(size_t)i * NN + idx];
        sX[idx] = v;
        sXh[idx] = packh2(v, v);
    }
    if (t < HH) {
        float w0 = W1[3 * t + 0];
        float w1v = W1[3 * t + 1];
        float w2v = W1[3 * t + 2];
        sc0[t] = fmaf(w0 - w2v, xi, b1[t]);
        sw12[t] = w1v + w2v;
    }
    float b3v = b3[0];

    // W2 B-fragments register-resident (f16x2), m16n8k16 col-major B layout.
    unsigned rB[2][4][2];
#pragma unroll
    for (int kt = 0; kt < 2; kt++)
#pragma unroll
        for (int nt = 0; nt < 4; nt++) {
            const float* wrow = W2 + (nt * 8 + g) * HH + kt * 16 + 2 * q;
            rB[kt][nt][0] = packh2(wrow[0], wrow[1]);
            rB[kt][nt][1] = packh2(wrow[8], wrow[9]);
        }
    // b2 seed, packed for this lane's accumulator columns m = nt*8+2q, +1
    unsigned b2h[4];
#pragma unroll
    for (int nt = 0; nt < 4; nt++)
        b2h[nt] = packh2(b2[nt * 8 + 2 * q], b2[nt * 8 + 2 * q + 1]);
    // Layer-3 B-fragment over k=m(hidden): column n=0 carries W3, others zero.
    unsigned rW3[2][2];
    if (g == 0) {
        rW3[0][0] = packh2(W3[2 * q], W3[2 * q + 1]);
        rW3[0][1] = packh2(W3[2 * q + 8], W3[2 * q + 9]);
        rW3[1][0] = packh2(W3[2 * q + 16], W3[2 * q + 17]);
        rW3[1][1] = packh2(W3[2 * q + 24], W3[2 * q + 25]);
    } else {
        rW3[0][0] = rW3[0][1] = rW3[1][0] = rW3[1][1] = 0u;
    }
    __syncthreads();

    // Layer-1 packed constants for this lane's 4 k-pairs: k0(p) = 2q + 8p
    unsigned c0h[4], w12h[4];
#pragma unroll
    for (int p = 0; p < 4; p++) {
        int k0 = 2 * q + 8 * p;
        c0h[p] = packh2(sc0[k0], sc0[k0 + 1]);
        w12h[p] = packh2(sw12[k0], sw12[k0 + 1]);
    }

    float acc = 0.f;
    bool lead = (q == 0);

#pragma unroll
    for (int tile = 0; tile < 8; tile++) {
        int jb = (tile * 8 + warp) * 16;
        unsigned xh1 = sXh[jb + g];
        unsigned xh2 = sXh[jb + g + 8];

        // Layer 1: A-fragments directly (aG = row g, aH = row g+8)
        unsigned aG[4], aH[4];
#pragma unroll
        for (int p = 0; p < 4; p++) {
            aG[p] = tanh_h2(hfma2(w12h[p], xh1, c0h[p]));
            aH[p] = tanh_h2(hfma2(w12h[p], xh2, c0h[p]));
        }

        // Layer 2: f16 accumulators (packed pairs), seeded with b2
        unsigned d0[4], d1[4];
#pragma unroll
        for (int nt = 0; nt < 4; nt++) {
            d0[nt] = b2h[nt];
            d1[nt] = b2h[nt];
        }
#pragma unroll
        for (int nt = 0; nt < 4; nt++)
            mma_f16h(d0[nt], d1[nt],
                     aG[0], aH[0], aG[1], aH[1], rB[0][nt][0], rB[0][nt][1]);
#pragma unroll
        for (int nt = 0; nt < 4; nt++)
            mma_f16h(d0[nt], d1[nt],
                     aG[2], aH[2], aG[3], aH[3], rB[1][nt][0], rB[1][nt][1]);

        // tanh directly on packed preacts; results are layer-3 A-fragments
        unsigned th1[4], th2[4];
#pragma unroll
        for (int nt = 0; nt < 4; nt++) {
            th1[nt] = tanh_h2(d0[nt]);  // row g
            th2[nt] = tanh_h2(d1[nt]);  // row g+8
        }

        // Layer 3 via MMA: raw = b3 + sum_m W3[m]*tanh(...) in col 0 (q==0 lanes)
        float r0 = b3v, r1 = b3v, r2 = b3v, r3 = b3v;
        mma_f16(r0, r1, r2, r3, th1[0], th2[0], th1[1], th2[1],
                rW3[0][0], rW3[0][1]);
        mma_f16(r0, r1, r2, r3, th1[2], th2[2], th1[3], th2[3],
                rW3[1][0], rW3[1][1]);

        // alpha = 2*sigmoid(raw) = 1 + tanh(raw/2); both alphas in one f16x2 tanh
        unsigned ah = tanh_h2(packh2(0.5f * r0, 0.5f * r2));
        float al1 = 1.f + hlo(ah);
        float al2 = 1.f + hhi(ah);

        int j1 = jb + g, j2 = jb + g + 8;
        float xj1 = sX[j1], xj2 = sX[j2];
        float c = sA[j1] * al1 * (xj1 - xi) + sA[j2] * al2 * (xj2 - xi);
        acc += lead ? c : 0.f;   // raw is only valid on q==0 lanes
    }

    // block reduction over 256 threads
#pragma unroll
    for (int o = 16; o; o >>= 1) acc += __shfl_xor_sync(0xffffffffu, acc, o);
    if (lane == 0) warpsum[warp] = acc;
    __syncthreads();
    if (t == 0) {
        float s = 0.f;
#pragma unroll
        for (int w = 0; w < 8; w++) s += warpsum[w];
        out[b * NN + i] = fmaf(0.1f, s, xi);
    }
}

extern "C" void kernel_launch(void* const* d_in, const int* in_sizes, int n_in,
                              void* d_out, int out_size) {
    (void)in_sizes; (void)n_in; (void)out_size;
    const float* x  = (const float*)d_in[0];
    const float* Th = (const float*)d_in[1];
    const float* W1 = (const float*)d_in[2];
    const float* b1 = (const float*)d_in[3];
    const float* W2 = (const float*)d_in[4];
    const float* b2 = (const float*)d_in[5];
    const float* W3 = (const float*)d_in[6];
    const float* b3 = (const float*)d_in[7];
    float* out = (float*)d_out;

    softmax_kernel<<<NN, 256>>>(Th);
    agg_kernel<<<BB * NN, 256>>>(x, W1, b1, W2, b2, W3, b3, out);
}

// round 8
// speedup vs baseline: 3.7803x; 1.0345x over previous
#include <cuda_runtime.h>

#define NN 1024
#define BB 4
#define HH 32

// 4 MB scratch for the normalized, diagonal-masked softmax adjacency.
__device__ float g_A[NN * NN];

// ---------------- f16x2 helpers ----------------
static __device__ __forceinline__ unsigned packh2(float lo, float hi) {
    unsigned r;  // first PTX source -> upper half
    asm("cvt.rn.f16x2.f32 %0, %1, %2;" : "=r"(r) : "f"(hi), "f"(lo));
    return r;
}
static __device__ __forceinline__ unsigned tanh_h2(unsigned v) {
    unsigned r;
    asm("tanh.approx.f16x2 %0, %1;" : "=r"(r) : "r"(v));
    return r;
}
static __device__ __forceinline__ unsigned hfma2(unsigned a, unsigned b, unsigned c) {
    unsigned d;
    asm("fma.rn.f16x2 %0, %1, %2, %3;" : "=r"(d) : "r"(a), "r"(b), "r"(c));
    return d;
}
static __device__ __forceinline__ float hlo(unsigned v) {
    float f;
    asm("{.reg .f16 l,h; mov.b32 {l,h}, %1; cvt.f32.f16 %0, l;}" : "=f"(f) : "r"(v));
    return f;
}
static __device__ __forceinline__ float hhi(unsigned v) {
    float f;
    asm("{.reg .f16 l,h; mov.b32 {l,h}, %1; cvt.f32.f16 %0, h;}" : "=f"(f) : "r"(v));
    return f;
}
// D(f16) += A(m16k16 f16) * B(k16n8 f16): C/D packed f16x2 (2 regs).
static __device__ __forceinline__ void mma_f16h(
    unsigned& d0, unsigned& d1,
    unsigned a0, unsigned a1, unsigned a2, unsigned a3,
    unsigned b0, unsigned b1) {
    asm("mma.sync.aligned.m16n8k16.row.col.f16.f16.f16.f16 "
        "{%0,%1},{%2,%3,%4,%5},{%6,%7},{%0,%1};"
        : "+r"(d0), "+r"(d1)
        : "r"(a0), "r"(a1), "r"(a2), "r"(a3), "r"(b0), "r"(b1));
}
// D(f32) += A(m16k16 f16) * B(k16n8 f16), fp32 accumulate.
static __device__ __forceinline__ void mma_f16(
    float& d0, float& d1, float& d2, float& d3,
    unsigned a0, unsigned a1, unsigned a2, unsigned a3,
    unsigned b0, unsigned b1) {
    asm("mma.sync.aligned.m16n8k16.row.col.f32.f16.f16.f32 "
        "{%0,%1,%2,%3},{%4,%5,%6,%7},{%8,%9},{%0,%1,%2,%3};"
        : "+f"(d0), "+f"(d1), "+f"(d2), "+f"(d3)
        : "r"(a0), "r"(a1), "r"(a2), "r"(a3), "r"(b0), "r"(b1));
}

// ---------------- Kernel 1: masked row softmax of Theta -> g_A ----------------
__global__ __launch_bounds__(256) void softmax_kernel(const float* __restrict__ Theta) {
    int i = blockIdx.x;
    int t = threadIdx.x;
    const float* row = Theta + (size_t)i * NN;

    float vals[4];
    float m = -3.4e38f;
#pragma unroll
    for (int u = 0; u < 4; u++) {
        vals[u] = row[t + 256 * u];
        m = fmaxf(m, vals[u]);
    }
#pragma unroll
    for (int o = 16; o; o >>= 1) m = fmaxf(m, __shfl_xor_sync(0xffffffffu, m, o));

    __shared__ float redmax[8], redsum[8];
    if ((t & 31) == 0) redmax[t >> 5] = m;
    __syncthreads();
    float m0 = redmax[0];
#pragma unroll
    for (int w = 1; w < 8; w++) m0 = fmaxf(m0, redmax[w]);

    float s = 0.f;
#pragma unroll
    for (int u = 0; u < 4; u++) {
        int j = t + 256 * u;
        float e = __expf(vals[u] - m0);
        if (j == i) e = 0.f;
        vals[u] = e;
        s += e;
    }
#pragma unroll
    for (int o = 16; o; o >>= 1) s += __shfl_xor_sync(0xffffffffu, s, o);
    if ((t & 31) == 0) redsum[t >> 5] = s;
    __syncthreads();
    float tot = 0.f;
#pragma unroll
    for (int w = 0; w < 8; w++) tot += redsum[w];
    float inv = 1.0f / tot;
#pragma unroll
    for (int u = 0; u < 4; u++) g_A[(size_t)i * NN + t + 256 * u] = vals[u] * inv;
}

// ---------------- Kernel 2: pairwise MLP, all GEMMs on tensor pipe ----------------
// One block per (b-pair, i): grid 2048. Inner loop over 2 batches shares the
// A row (direct LDG, no staging) and the per-block W fragment setup.
__global__ __launch_bounds__(256, 4) void agg_kernel(
    const float* __restrict__ x,
    const float* __restrict__ W1, const float* __restrict__ b1,
    const float* __restrict__ W2, const float* __restrict__ b2,
    const float* __restrict__ W3, const float* __restrict__ b3,
    float* __restrict__ out) {
    __shared__ float sX[2][NN];        // x rows for both batches
    __shared__ unsigned sXh[2][NN];    // pre-packed f16x2 {x,x}
    __shared__ float sc0[2][HH];       // per-b: (W1[k][0]-W1[k][2])*xi + b1[k]
    __shared__ float sw12[HH];         // W1[k][1]+W1[k][2]
    __shared__ float warpsum[2][8];

    int t = threadIdx.x;
    int lane = t & 31, warp = t >> 5;
    int g = lane >> 2;   // groupID
    int q = lane & 3;    // threadID_in_group
    int bi = blockIdx.x;
    int b0 = (bi >> 10) << 1;          // first batch of the pair
    int i = bi & (NN - 1);
    const float* Arow = g_A + (size_t)i * NN;

    for (int idx = t; idx < 2 * NN; idx += 256) {
        int bl = idx >> 10, j = idx & (NN - 1);
        float v = x[(b0 + bl) * NN + j];
        sX[bl][j] = v;
        sXh[bl][j] = packh2(v, v);
    }
    if (t < HH) {
        float w0 = W1[3 * t + 0];
        float w1v = W1[3 * t + 1];
        float w2v = W1[3 * t + 2];
        float wd = w0 - w2v;
        float bb1 = b1[t];
        sc0[0][t] = fmaf(wd, x[(b0 + 0) * NN + i], bb1);
        sc0[1][t] = fmaf(wd, x[(b0 + 1) * NN + i], bb1);
        sw12[t] = w1v + w2v;
    }
    float b3v = b3[0];

    // W2 B-fragments register-resident (f16x2), m16n8k16 col-major B layout.
    unsigned rB[2][4][2];
#pragma unroll
    for (int kt = 0; kt < 2; kt++)
#pragma unroll
        for (int nt = 0; nt < 4; nt++) {
            const float* wrow = W2 + (nt * 8 + g) * HH + kt * 16 + 2 * q;
            rB[kt][nt][0] = packh2(wrow[0], wrow[1]);
            rB[kt][nt][1] = packh2(wrow[8], wrow[9]);
        }
    // b2 seed, packed for this lane's accumulator columns m = nt*8+2q, +1
    unsigned b2h[4];
#pragma unroll
    for (int nt = 0; nt < 4; nt++)
        b2h[nt] = packh2(b2[nt * 8 + 2 * q], b2[nt * 8 + 2 * q + 1]);
    // Layer-3 B-fragment over k=m(hidden): column n=0 carries W3, others zero.
    unsigned rW3[2][2];
    if (g == 0) {
        rW3[0][0] = packh2(W3[2 * q], W3[2 * q + 1]);
        rW3[0][1] = packh2(W3[2 * q + 8], W3[2 * q + 9]);
        rW3[1][0] = packh2(W3[2 * q + 16], W3[2 * q + 17]);
        rW3[1][1] = packh2(W3[2 * q + 24], W3[2 * q + 25]);
    } else {
        rW3[0][0] = rW3[0][1] = rW3[1][0] = rW3[1][1] = 0u;
    }
    // Layer-1 shared weight packs (b-independent): k0(p) = 2q + 8p
    unsigned w12h[4];
    __syncthreads();
#pragma unroll
    for (int p = 0; p < 4; p++) {
        int k0 = 2 * q + 8 * p;
        w12h[p] = packh2(sw12[k0], sw12[k0 + 1]);
    }

    bool lead = (q == 0);
    float accs[2];

#pragma unroll
    for (int bb = 0; bb < 2; bb++) {
        float xi = sX[bb][i];
        unsigned c0h[4];
#pragma unroll
        for (int p = 0; p < 4; p++) {
            int k0 = 2 * q + 8 * p;
            c0h[p] = packh2(sc0[bb][k0], sc0[bb][k0 + 1]);
        }

        float acc = 0.f;
#pragma unroll
        for (int tile = 0; tile < 8; tile++) {
            int jb = (tile * 8 + warp) * 16;
            int j1 = jb + g, j2 = jb + g + 8;
            // issue A loads first; latency hides behind the MLP chain
            float aj1 = __ldg(Arow + j1);
            float aj2 = __ldg(Arow + j2);
            unsigned xh1 = sXh[bb][j1];
            unsigned xh2 = sXh[bb][j2];

            // Layer 1: A-fragments directly (aG = row g, aH = row g+8)
            unsigned aG[4], aH[4];
#pragma unroll
            for (int p = 0; p < 4; p++) {
                aG[p] = tanh_h2(hfma2(w12h[p], xh1, c0h[p]));
                aH[p] = tanh_h2(hfma2(w12h[p], xh2, c0h[p]));
            }

            // Layer 2: f16 accumulators (packed pairs), seeded with b2
            unsigned d0[4], d1[4];
#pragma unroll
            for (int nt = 0; nt < 4; nt++) {
                d0[nt] = b2h[nt];
                d1[nt] = b2h[nt];
            }
#pragma unroll
            for (int nt = 0; nt < 4; nt++)
                mma_f16h(d0[nt], d1[nt],
                         aG[0], aH[0], aG[1], aH[1], rB[0][nt][0], rB[0][nt][1]);
#pragma unroll
            for (int nt = 0; nt < 4; nt++)
                mma_f16h(d0[nt], d1[nt],
                         aG[2], aH[2], aG[3], aH[3], rB[1][nt][0], rB[1][nt][1]);

            // tanh on packed preacts; results are layer-3 A-fragments
            unsigned th1[4], th2[4];
#pragma unroll
            for (int nt = 0; nt < 4; nt++) {
                th1[nt] = tanh_h2(d0[nt]);  // row g
                th2[nt] = tanh_h2(d1[nt]);  // row g+8
            }

            // Layer 3 via MMA: raw lands in col 0 (q==0 lanes)
            float r0 = b3v, r1 = b3v, r2 = b3v, r3 = b3v;
            mma_f16(r0, r1, r2, r3, th1[0], th2[0], th1[1], th2[1],
                    rW3[0][0], rW3[0][1]);
            mma_f16(r0, r1, r2, r3, th1[2], th2[2], th1[3], th2[3],
                    rW3[1][0], rW3[1][1]);

            // alpha = 2*sigmoid(raw) = 1 + tanh(raw/2)
            unsigned ah = tanh_h2(packh2(0.5f * r0, 0.5f * r2));
            float al1 = 1.f + hlo(ah);
            float al2 = 1.f + hhi(ah);

            float xj1 = sX[bb][j1], xj2 = sX[bb][j2];
            float c = aj1 * al1 * (xj1 - xi) + aj2 * al2 * (xj2 - xi);
            acc += lead ? c : 0.f;   // raw only valid on q==0 lanes
        }
        accs[bb] = acc;
    }

    // block reduction for both batches
#pragma unroll
    for (int bb = 0; bb < 2; bb++) {
        float a = accs[bb];
#pragma unroll
        for (int o = 16; o; o >>= 1) a += __shfl_xor_sync(0xffffffffu, a, o);
        if (lane == 0) warpsum[bb][warp] = a;
    }
    __syncthreads();
    if (t < 2) {
        float s = 0.f;
#pragma unroll
        for (int w = 0; w < 8; w++) s += warpsum[t][w];
        out[(b0 + t) * NN + i] = fmaf(0.1f, s, sX[t][i]);
    }
}

extern "C" void kernel_launch(void* const* d_in, const int* in_sizes, int n_in,
                              void* d_out, int out_size) {
    (void)in_sizes; (void)n_in; (void)out_size;
    const float* x  = (const float*)d_in[0];
    const float* Th = (const float*)d_in[1];
    const float* W1 = (const float*)d_in[2];
    const float* b1 = (const float*)d_in[3];
    const float* W2 = (const float*)d_in[4];
    const float* b2 = (const float*)d_in[5];
    const float* W3 = (const float*)d_in[6];
    const float* b3 = (const float*)d_in[7];
    float* out = (float*)d_out;

    softmax_kernel<<<NN, 256>>>(Th);
    agg_kernel<<<(BB / 2) * NN, 256>>>(x, W1, b1, W2, b2, W3, b3, out);
}